// round 2
// baseline (speedup 1.0000x reference)
#include <cuda_runtime.h>

#define NSP 4096
#define CDIM 256
#define BQ 64
#define BK 64
#define NB 8

// Scratch for projected Q, K, V : [B][C][N] fp32 (33.5 MB each)
__device__ float g_Q[(size_t)NB * CDIM * NSP];
__device__ float g_K[(size_t)NB * CDIM * NSP];
__device__ float g_V[(size_t)NB * CDIM * NSP];

typedef unsigned long long u64;

__device__ __forceinline__ u64 ffma2(u64 a, u64 b, u64 c) {
    u64 d;
    asm("fma.rn.f32x2 %0, %1, %2, %3;" : "=l"(d) : "l"(a), "l"(b), "l"(c));
    return d;
}
__device__ __forceinline__ u64 fmul2(u64 a, u64 b) {
    u64 d;
    asm("mul.rn.f32x2 %0, %1, %2;" : "=l"(d) : "l"(a), "l"(b));
    return d;
}
__device__ __forceinline__ u64 pack2(float lo, float hi) {
    u64 d;
    asm("mov.b64 %0, {%1, %2};" : "=l"(d) : "f"(lo), "f"(hi));
    return d;
}
__device__ __forceinline__ float2 unpack2(u64 v) {
    float lo, hi;
    asm("mov.b64 {%0, %1}, %2;" : "=f"(lo), "=f"(hi) : "l"(v));
    return make_float2(lo, hi);
}

// ---------------------------------------------------------------------------
// Kernel 1: 1x1-conv projections.  Out[b][o][n] = sum_c W[o][c] * X[b][c][n] + bias[o]
// grid: (N/64, B, 12)  z: proj = z>>2 (0:Q,1:K,2:V), o-tile = z&3.  256 threads.
// ---------------------------------------------------------------------------
__global__ __launch_bounds__(256) void proj_kernel(
    const float* __restrict__ x, const float* __restrict__ attr,
    const float* __restrict__ Wq, const float* __restrict__ bq,
    const float* __restrict__ Wk, const float* __restrict__ bk,
    const float* __restrict__ Wv, const float* __restrict__ bv)
{
    __shared__ __align__(16) float Xs[32 * 64];
    __shared__ __align__(16) float Wt[32 * 68];

    const int tid = threadIdx.x;
    const int tx = tid & 15, ty = tid >> 4;
    const int n0 = blockIdx.x * 64;
    const int bb = blockIdx.y;
    const int z = blockIdx.z;
    const int proj = z >> 2;
    const int o0 = (z & 3) * 64;

    const float* X;
    const float* W;
    const float* bias;
    float* dst;
    if (proj == 0)      { X = x;    W = Wq; bias = bq; dst = g_Q; }
    else if (proj == 1) { X = attr; W = Wk; bias = bk; dst = g_K; }
    else                { X = attr; W = Wv; bias = bv; dst = g_V; }

    const float* Xb = X + (size_t)bb * CDIM * NSP;

    u64 acc[4][2];
    #pragma unroll
    for (int r = 0; r < 4; r++) {
        float bv0 = bias[o0 + 4 * ty + r];
        acc[r][0] = pack2(bv0, bv0);
        acc[r][1] = acc[r][0];
    }

    for (int ck = 0; ck < 8; ck++) {
        const int c0 = ck * 32;
        __syncthreads();
        // X chunk [32 c][64 n] -> Xs, coalesced
        {
            int row = tid >> 3, col = (tid & 7) * 4;
            const float* src = Xb + (size_t)(c0 + row) * NSP + n0;
            *(float4*)&Xs[row * 64 + col]      = *(const float4*)&src[col];
            *(float4*)&Xs[row * 64 + col + 32] = *(const float4*)&src[col + 32];
        }
        // W chunk transposed: Wt[cc][oo] = W[o0+oo][c0+cc]
        {
            int oo = tid >> 2, cc0 = (tid & 3) * 8;
            const float* src = W + (size_t)(o0 + oo) * CDIM + c0 + cc0;
            float4 a = *(const float4*)&src[0];
            float4 c4 = *(const float4*)&src[4];
            Wt[(cc0 + 0) * 68 + oo] = a.x;
            Wt[(cc0 + 1) * 68 + oo] = a.y;
            Wt[(cc0 + 2) * 68 + oo] = a.z;
            Wt[(cc0 + 3) * 68 + oo] = a.w;
            Wt[(cc0 + 4) * 68 + oo] = c4.x;
            Wt[(cc0 + 5) * 68 + oo] = c4.y;
            Wt[(cc0 + 6) * 68 + oo] = c4.z;
            Wt[(cc0 + 7) * 68 + oo] = c4.w;
        }
        __syncthreads();

        #pragma unroll 8
        for (int cc = 0; cc < 32; cc++) {
            float4 wv = *(float4*)&Wt[cc * 68 + 4 * ty];
            ulonglong2 xv = *(ulonglong2*)&Xs[cc * 64 + 4 * tx];
            u64 w0 = pack2(wv.x, wv.x), w1 = pack2(wv.y, wv.y);
            u64 w2 = pack2(wv.z, wv.z), w3 = pack2(wv.w, wv.w);
            acc[0][0] = ffma2(w0, xv.x, acc[0][0]); acc[0][1] = ffma2(w0, xv.y, acc[0][1]);
            acc[1][0] = ffma2(w1, xv.x, acc[1][0]); acc[1][1] = ffma2(w1, xv.y, acc[1][1]);
            acc[2][0] = ffma2(w2, xv.x, acc[2][0]); acc[2][1] = ffma2(w2, xv.y, acc[2][1]);
            acc[3][0] = ffma2(w3, xv.x, acc[3][0]); acc[3][1] = ffma2(w3, xv.y, acc[3][1]);
        }
    }

    #pragma unroll
    for (int r = 0; r < 4; r++) {
        float2 a = unpack2(acc[r][0]);
        float2 c2 = unpack2(acc[r][1]);
        float4 res = make_float4(a.x, a.y, c2.x, c2.y);
        *(float4*)&dst[((size_t)bb * CDIM + o0 + 4 * ty + r) * NSP + n0 + 4 * tx] = res;
    }
}

// ---------------------------------------------------------------------------
// Kernel 2: flash attention (no scale) + residual add.
// grid: (N/BQ, B), 256 threads (16x16).  1 CTA/SM (209 KB smem).
//   S[i][j] = sum_c Q[c][i] K[c][j] ; softmax over j (online) ;
//   O[i][c] = sum_j P[i][j] V[c][j] ; out = O/l + x
// ---------------------------------------------------------------------------
#define SM_Q  0
#define SM_K  16384
#define SM_V  32768
#define SM_P  49152
#define SM_FLOATS (49152 + 64 * 68)
#define SM_BYTES  (SM_FLOATS * 4)

__global__ __launch_bounds__(256) void attn_kernel(
    const float* __restrict__ x, float* __restrict__ out)
{
    extern __shared__ __align__(16) float sm[];
    float* Qs = sm + SM_Q;   // [256 c][64 i]
    float* Ks = sm + SM_K;   // [256 c][64 j]
    float* Vt = sm + SM_V;   // [64 j][256 c]
    float* Pt = sm + SM_P;   // [64 j][68] (i fast)

    const int tid = threadIdx.x;
    const int tx = tid & 15, ty = tid >> 4;
    const int bb = blockIdx.y;
    const int n0 = blockIdx.x * BQ;

    const float* Qg = g_Q + (size_t)bb * CDIM * NSP;
    const float* Kg = g_K + (size_t)bb * CDIM * NSP;
    const float* Vg = g_V + (size_t)bb * CDIM * NSP;

    // Load Q tile [256][64], coalesced
    #pragma unroll
    for (int it = 0; it < 16; it++) {
        int c = it * 16 + ty;
        *(float4*)&Qs[c * 64 + 4 * tx] =
            *(const float4*)&Qg[(size_t)c * NSP + n0 + 4 * tx];
    }

    u64 Oa[4][4][2];
    #pragma unroll
    for (int r = 0; r < 4; r++)
        #pragma unroll
        for (int pp = 0; pp < 4; pp++) { Oa[r][pp][0] = 0ULL; Oa[r][pp][1] = 0ULL; }

    float m[4], l[4];
    #pragma unroll
    for (int r = 0; r < 4; r++) { m[r] = -1e30f; l[r] = 0.0f; }

    for (int kt = 0; kt < NSP / BK; kt++) {
        const int k0 = kt * BK;
        __syncthreads();  // previous iteration done with Ks/Vt/Pt (also covers Q load)

        // K tile [256 c][64 j]
        #pragma unroll
        for (int it = 0; it < 16; it++) {
            int c = it * 16 + ty;
            *(float4*)&Ks[c * 64 + 4 * tx] =
                *(const float4*)&Kg[(size_t)c * NSP + k0 + 4 * tx];
        }
        // V tile transposed -> Vt[j][c]; conflict-free stores (lanes vary c)
        {
            const float* src = Vg + (size_t)tid * NSP + k0;
            #pragma unroll
            for (int j4 = 0; j4 < 16; j4++) {
                float4 v = *(const float4*)&src[4 * j4];
                Vt[(4 * j4 + 0) * 256 + tid] = v.x;
                Vt[(4 * j4 + 1) * 256 + tid] = v.y;
                Vt[(4 * j4 + 2) * 256 + tid] = v.z;
                Vt[(4 * j4 + 3) * 256 + tid] = v.w;
            }
        }
        __syncthreads();

        // ---- S = Q^T K : thread tile i=4ty+r, j=4tx+(2h+e) ----
        u64 Sa[4][2];
        #pragma unroll
        for (int r = 0; r < 4; r++) { Sa[r][0] = 0ULL; Sa[r][1] = 0ULL; }

        #pragma unroll 8
        for (int c = 0; c < CDIM; c++) {
            float4 qv = *(float4*)&Qs[c * 64 + 4 * ty];
            ulonglong2 kv = *(ulonglong2*)&Ks[c * 64 + 4 * tx];
            u64 q0 = pack2(qv.x, qv.x), q1 = pack2(qv.y, qv.y);
            u64 q2 = pack2(qv.z, qv.z), q3 = pack2(qv.w, qv.w);
            Sa[0][0] = ffma2(q0, kv.x, Sa[0][0]); Sa[0][1] = ffma2(q0, kv.y, Sa[0][1]);
            Sa[1][0] = ffma2(q1, kv.x, Sa[1][0]); Sa[1][1] = ffma2(q1, kv.y, Sa[1][1]);
            Sa[2][0] = ffma2(q2, kv.x, Sa[2][0]); Sa[2][1] = ffma2(q2, kv.y, Sa[2][1]);
            Sa[3][0] = ffma2(q3, kv.x, Sa[3][0]); Sa[3][1] = ffma2(q3, kv.y, Sa[3][1]);
        }

        // ---- online softmax over this key tile ----
        #pragma unroll
        for (int r = 0; r < 4; r++) {
            float2 s0 = unpack2(Sa[r][0]);
            float2 s1 = unpack2(Sa[r][1]);
            float rm = fmaxf(fmaxf(s0.x, s0.y), fmaxf(s1.x, s1.y));
            #pragma unroll
            for (int o = 8; o > 0; o >>= 1)
                rm = fmaxf(rm, __shfl_xor_sync(0xffffffffu, rm, o));
            float mn = fmaxf(m[r], rm);
            float sc = __expf(m[r] - mn);
            m[r] = mn;
            float p0 = __expf(s0.x - mn), p1 = __expf(s0.y - mn);
            float p2 = __expf(s1.x - mn), p3 = __expf(s1.y - mn);
            float rs = (p0 + p1) + (p2 + p3);
            #pragma unroll
            for (int o = 8; o > 0; o >>= 1)
                rs += __shfl_xor_sync(0xffffffffu, rs, o);
            l[r] = l[r] * sc + rs;
            u64 sc2 = pack2(sc, sc);
            #pragma unroll
            for (int pp = 0; pp < 4; pp++) {
                Oa[r][pp][0] = fmul2(Oa[r][pp][0], sc2);
                Oa[r][pp][1] = fmul2(Oa[r][pp][1], sc2);
            }
            Pt[(4 * tx + 0) * 68 + 4 * ty + r] = p0;
            Pt[(4 * tx + 1) * 68 + 4 * ty + r] = p1;
            Pt[(4 * tx + 2) * 68 + 4 * ty + r] = p2;
            Pt[(4 * tx + 3) * 68 + 4 * ty + r] = p3;
        }
        __syncthreads();

        // ---- O += P * V : thread tile i=4ty+r, c=64pp+4tx+(2h+e) ----
        #pragma unroll 2
        for (int j = 0; j < BK; j++) {
            float4 pv = *(float4*)&Pt[j * 68 + 4 * ty];
            u64 pr0 = pack2(pv.x, pv.x), pr1 = pack2(pv.y, pv.y);
            u64 pr2 = pack2(pv.z, pv.z), pr3 = pack2(pv.w, pv.w);
            #pragma unroll
            for (int pp = 0; pp < 4; pp++) {
                ulonglong2 vv = *(ulonglong2*)&Vt[j * 256 + 64 * pp + 4 * tx];
                Oa[0][pp][0] = ffma2(pr0, vv.x, Oa[0][pp][0]);
                Oa[0][pp][1] = ffma2(pr0, vv.y, Oa[0][pp][1]);
                Oa[1][pp][0] = ffma2(pr1, vv.x, Oa[1][pp][0]);
                Oa[1][pp][1] = ffma2(pr1, vv.y, Oa[1][pp][1]);
                Oa[2][pp][0] = ffma2(pr2, vv.x, Oa[2][pp][0]);
                Oa[2][pp][1] = ffma2(pr2, vv.y, Oa[2][pp][1]);
                Oa[3][pp][0] = ffma2(pr3, vv.x, Oa[3][pp][0]);
                Oa[3][pp][1] = ffma2(pr3, vv.y, Oa[3][pp][1]);
            }
        }
    }

    // ---- epilogue: O/l through smem transpose, + x, coalesced store ----
    __syncthreads();
    float* Os = sm;  // [64 i][257]
    #pragma unroll
    for (int r = 0; r < 4; r++) {
        float invl = 1.0f / l[r];
        int i = 4 * ty + r;
        #pragma unroll
        for (int pp = 0; pp < 4; pp++) {
            float2 a = unpack2(Oa[r][pp][0]);
            float2 c2 = unpack2(Oa[r][pp][1]);
            int cb = 64 * pp + 4 * tx;
            Os[i * 257 + cb + 0] = a.x * invl;
            Os[i * 257 + cb + 1] = a.y * invl;
            Os[i * 257 + cb + 2] = c2.x * invl;
            Os[i * 257 + cb + 3] = c2.y * invl;
        }
    }
    __syncthreads();

    const float* xb = x + (size_t)bb * CDIM * NSP;
    float* ob = out + (size_t)bb * CDIM * NSP;
    const int i = tid & 63;
    const int csub = tid >> 6;
    #pragma unroll 4
    for (int c0 = 0; c0 < CDIM; c0 += 4) {
        int c = c0 + csub;
        size_t g = (size_t)c * NSP + n0 + i;
        ob[g] = Os[i * 257 + c] + xb[g];
    }
}

// ---------------------------------------------------------------------------
extern "C" void kernel_launch(void* const* d_in, const int* in_sizes, int n_in,
                              void* d_out, int out_size)
{
    const float* x    = (const float*)d_in[0];
    const float* attr = (const float*)d_in[1];
    const float* Wq   = (const float*)d_in[2];
    const float* bq   = (const float*)d_in[3];
    const float* Wk   = (const float*)d_in[4];
    const float* bk   = (const float*)d_in[5];
    const float* Wv   = (const float*)d_in[6];
    const float* bv   = (const float*)d_in[7];
    float* out = (float*)d_out;

    cudaFuncSetAttribute(attn_kernel,
                         cudaFuncAttributeMaxDynamicSharedMemorySize, SM_BYTES);

    dim3 gp(NSP / 64, NB, 12);
    proj_kernel<<<gp, 256>>>(x, attr, Wq, bq, Wk, bk, Wv, bv);

    dim3 ga(NSP / BQ, NB);
    attn_kernel<<<ga, 256, SM_BYTES>>>(x, out);
}